// round 15
// baseline (speedup 1.0000x reference)
#include <cuda_runtime.h>

// Gray-Scott residual: channel-split Tc=2, ALL loads as single aligned LDG.128 per
// row per thread; halo columns redistributed via warp shfl (edge lanes load directly).
// ty selects channel (0->f_u, 1->f_v); coupling term re-reads other-channel centers
// (L1-hot). input (20,8,3,256,256) f32 -> f_u, f_v each (20,8,1,252,252) concat.

#define T_DIM 20
#define B_DIM 8
#define WW 256
#define OH 252
#define OW 252
#define CS 65536
#define OPLANE (OH * OW)           // 63504
#define NOUT (T_DIM * B_DIM * OPLANE)

#define C1f (4.0f / 3.0f)
#define C2f (-1.0f / 12.0f)
#define INV_DX2 40.96f

__device__ __forceinline__ float4 ldf4(const float* __restrict__ p)
{
    return *reinterpret_cast<const float4*>(p);
}

// Expand own aligned float4 (cols col0..col0+3) to middle-4 (cols +2..+5).
__device__ __forceinline__ void exp4(float4 a, const float* __restrict__ p, bool edge,
                                     float c[4])
{
    float b0 = __shfl_down_sync(0xffffffffu, a.x, 1);
    float b1 = __shfl_down_sync(0xffffffffu, a.y, 1);
    if (edge) {
        const float2 e = *reinterpret_cast<const float2*>(p + 4);
        b0 = e.x; b1 = e.y;
    }
    c[0] = a.z; c[1] = a.w; c[2] = b0; c[3] = b1;
}

// Expand own aligned float4 to full 8 columns (cols col0..col0+7).
__device__ __forceinline__ void exp8(float4 a, const float* __restrict__ p, bool edge,
                                     float c[8])
{
    float b0 = __shfl_down_sync(0xffffffffu, a.x, 1);
    float b1 = __shfl_down_sync(0xffffffffu, a.y, 1);
    float b2 = __shfl_down_sync(0xffffffffu, a.z, 1);
    float b3 = __shfl_down_sync(0xffffffffu, a.w, 1);
    if (edge) {
        const float4 e = *reinterpret_cast<const float4*>(p + 4);
        b0 = e.x; b1 = e.y; b2 = e.z; b3 = e.w;
    }
    c[0] = a.x; c[1] = a.y; c[2] = a.z; c[3] = a.w;
    c[4] = b0;  c[5] = b1;  c[6] = b2;  c[7] = b3;
}

// Full spatial stencil at one t (rows p..p+5W): scaled lap[8] + centers c[8].
// 6 aligned LDG.128 front-batched, then shfl expansion, then math.
__device__ __forceinline__ void spatial(const float* __restrict__ p, bool edge,
                                        float lap[8], float c[8])
{
    const float4 L0 = ldf4(p);
    const float4 L1 = ldf4(p + 1 * WW);
    const float4 L2 = ldf4(p + 2 * WW);
    const float4 L3 = ldf4(p + 3 * WW);
    const float4 L4 = ldf4(p + 4 * WW);
    const float4 L5 = ldf4(p + 5 * WW);

    float r2[8], r3[8], n0[4], n1[4], n4[4], n5[4];
    exp8(L2, p + 2 * WW, edge, r2);
    exp8(L3, p + 3 * WW, edge, r3);
    exp4(L0, p,          edge, n0);
    exp4(L1, p + 1 * WW, edge, n1);
    exp4(L4, p + 4 * WW, edge, n4);
    exp4(L5, p + 5 * WW, edge, n5);

    #pragma unroll
    for (int k = 0; k < 4; k++) {
        const float cc0 = r2[k + 2];
        const float cc1 = r3[k + 2];
        lap[k]     = (C1f * (r2[k + 1] + r2[k + 3] + n1[k] + cc1)
                    + C2f * (r2[k] + r2[k + 4] + n0[k] + n4[k])
                    - 5.0f * cc0) * INV_DX2;
        lap[k + 4] = (C1f * (r3[k + 1] + r3[k + 3] + cc0 + n4[k])
                    + C2f * (r3[k] + r3[k + 4] + n1[k] + n5[k])
                    - 5.0f * cc1) * INV_DX2;
        c[k]     = cc0;
        c[k + 4] = cc1;
    }
}

// Center-only tile (rows +2,+3, middle-4 cols) via 2 aligned LDG.128 + shfl.
__device__ __forceinline__ void centers(const float* __restrict__ p, bool edge,
                                        float c[8])
{
    const float4 L2 = ldf4(p + 2 * WW);
    const float4 L3 = ldf4(p + 3 * WW);
    exp4(L2, p + 2 * WW, edge, c);
    exp4(L3, p + 3 * WW, edge, c + 4);
}

// Store one channel's 2x4 residual tile.
__device__ __forceinline__ void emit1(float* __restrict__ base, int yy0, int col0,
                                      const float r[8])
{
    const size_t o = (size_t)yy0 * OW + col0;
    *reinterpret_cast<float4*>(base + o)      = make_float4(r[0], r[1], r[2], r[3]);
    *reinterpret_cast<float4*>(base + o + OW) = make_float4(r[4], r[5], r[6], r[7]);
}

__global__ __launch_bounds__(128) void grayscott_loss_kernel(
    const float* __restrict__ in, float* __restrict__ out)
{
    const int tx   = threadIdx.x;                 // 0..63
    const int ch   = threadIdx.y;                 // 0 = u (f_u), 1 = v (f_v); warp-uniform
    const int lane = tx & 31;
    const bool edge = (lane == 31) || (tx == 62);
    const int col0 = min(4 * tx, 248);            // tx==63 duplicates tx==62 (benign)
    const int yy0  = blockIdx.x * 2;              // output rows yy0, yy0+1
    const int bc   = blockIdx.y;                  // 0..79
    const int b    = bc & 7;
    const int a    = (bc >> 3) * 2;               // first t of chunk: 0,2,..,18

    const size_t sp_off = (size_t)yy0 * WW + col0;

    const size_t tbase_a = ((size_t)(a * B_DIM + b) * 3 + 1) * CS;
    const size_t tbase_b = ((size_t)((a + 1) * B_DIM + b) * 3 + 1) * CS;
    const int    chOff    = ch * CS;
    const int    otherOff = (1 - ch) * CS;

    const float* pA = in + tbase_a + chOff + sp_off;      // my channel, t=a
    const float* pB = in + tbase_b + chOff + sp_off;      // my channel, t=a+1

    // ---- own spatial stencils ----
    float lapA[8], cA[8], lapB[8], cB[8];
    spatial(pA, edge, lapA, cA);
    spatial(pB, edge, lapB, cB);

    // ---- other-channel centers (L1-hot) ----
    float oA[8], oB[8];
    centers(in + tbase_a + otherOff + sp_off, edge, oA);
    centers(in + tbase_b + otherOff + sp_off, edge, oB);

    // ---- own time-boundary centers ----
    float cm[8], cp[8];
    if (a > 0)
        centers(in + ((size_t)((a - 1) * B_DIM + b) * 3 + 1) * CS + chOff + sp_off, edge, cm);
    if (a + 2 < T_DIM)
        centers(in + ((size_t)((a + 2) * B_DIM + b) * 3 + 1) * CS + chOff + sp_off, edge, cp);

    // ---- reaction + diffusion partials ----
    const float D  = ch ? 0.08f : 0.16f;
    const float Ff = 0.06f, FpK = 0.122f;

    float pAr[8], pBr[8];
    #pragma unroll
    for (int k = 0; k < 8; k++) {
        const float uvvA = ch ? (oA[k] * cA[k] * cA[k]) : (cA[k] * oA[k] * oA[k]);
        const float uvvB = ch ? (oB[k] * cB[k] * cB[k]) : (cB[k] * oB[k] * oB[k]);
        const float reactA = ch ? (uvvA - FpK * cA[k]) : (Ff * (1.0f - cA[k]) - uvvA);
        const float reactB = ch ? (uvvB - FpK * cB[k]) : (Ff * (1.0f - cB[k]) - uvvB);
        pAr[k] = D * lapA[k] + reactA;
        pBr[k] = D * lapB[k] + reactB;
    }

    float* outMy = out + (size_t)ch * NOUT;

    // ---- residual at t = a ----
    {
        float r[8];
        if (a == 0) {
            #pragma unroll
            for (int k = 0; k < 8; k++)
                r[k] = pAr[k] + 30.0f * cA[k] - 40.0f * cB[k] + 10.0f * cp[k];
        } else {
            #pragma unroll
            for (int k = 0; k < 8; k++)
                r[k] = pAr[k] - 10.0f * (cB[k] - cm[k]);
        }
        emit1(outMy + (size_t)(a * B_DIM + b) * OPLANE, yy0, col0, r);
    }

    // ---- residual at t = a+1 ----
    {
        float r[8];
        if (a + 1 == T_DIM - 1) {
            #pragma unroll
            for (int k = 0; k < 8; k++)
                r[k] = pBr[k] - 30.0f * cB[k] + 40.0f * cA[k] - 10.0f * cm[k];
        } else {
            #pragma unroll
            for (int k = 0; k < 8; k++)
                r[k] = pBr[k] - 10.0f * (cp[k] - cA[k]);
        }
        emit1(outMy + (size_t)((a + 1) * B_DIM + b) * OPLANE, yy0, col0, r);
    }
}

extern "C" void kernel_launch(void* const* d_in, const int* in_sizes, int n_in,
                              void* d_out, int out_size)
{
    const float* in = (const float*)d_in[0];
    float* out = (float*)d_out;
    dim3 block(64, 2, 1);                        // ty=0 -> f_u warps, ty=1 -> f_v warps
    dim3 grid(OH / 2, B_DIM * (T_DIM / 2), 1);   // 126 x 80 = 10080 CTAs
    grayscott_loss_kernel<<<grid, block>>>(in, out);
}

// round 17
// speedup vs baseline: 1.1966x; 1.1966x over previous
#include <cuda_runtime.h>

// Gray-Scott residual: y-rolling register window, channel-split, Tc=1.
// Each thread owns 4 output cols and marches YT=14 output rows, keeping a 5-row
// window (3 full-8 rows + 2 middle-4 rows) in registers: one new full row load
// per step. Time derivative + coupling via center-4 ldn loads per step.
// ty selects channel (0->f_u, 1->f_v). No shfl, no smem, no barriers.
// input (20,8,3,256,256) f32 -> f_u, f_v each (20,8,1,252,252) concatenated.

#define T_DIM 20
#define B_DIM 8
#define WW 256
#define OH 252
#define OW 252
#define CS 65536
#define TS_ (B_DIM * 3 * CS)       // stride between consecutive t planes
#define OPLANE (OH * OW)           // 63504
#define NOUT (T_DIM * B_DIM * OPLANE)
#define YT 14                      // output rows per strip (252 = 18 * 14)

#define C1f (4.0f / 3.0f)
#define C2f (-1.0f / 12.0f)
#define INV_DX2 40.96f

// Exactly cols +2..+5 of one row via two aligned LDG.64.
__device__ __forceinline__ void ldn(const float* __restrict__ p, float n[4])
{
    const float2 a = *reinterpret_cast<const float2*>(p + 2);
    const float2 b = *reinterpret_cast<const float2*>(p + 4);
    n[0] = a.x; n[1] = a.y; n[2] = b.x; n[3] = b.y;
}

// Full 8 cols (col0..col0+7) via two aligned LDG.128.
__device__ __forceinline__ void ld8(const float* __restrict__ p, float c[8])
{
    const float4 a = *reinterpret_cast<const float4*>(p);
    const float4 b = *reinterpret_cast<const float4*>(p + 4);
    c[0] = a.x; c[1] = a.y; c[2] = a.z; c[3] = a.w;
    c[4] = b.x; c[5] = b.y; c[6] = b.z; c[7] = b.w;
}

__global__ __launch_bounds__(128) void grayscott_loss_kernel(
    const float* __restrict__ in, float* __restrict__ out)
{
    const int tx   = threadIdx.x;                 // 0..63
    const int ch   = threadIdx.y;                 // 0 = u (f_u), 1 = v (f_v)
    const int col0 = min(4 * tx, 248);            // tx==63 duplicates tx==62 (benign)
    const int y0   = blockIdx.x * YT;             // strip base output row
    const int bc   = blockIdx.y;                  // 0..159
    const int b    = bc & 7;
    const int t    = bc >> 3;

    // my channel plane at time t
    const float* __restrict__ base = in + ((size_t)(t * B_DIM + b) * 3 + 1 + ch) * CS;
    const float* __restrict__ po   = base + (ch ? -CS : CS);   // other channel, same t

    // time-derivative scheme: r = p - (al*c + be*A + ga*B)
    int dA, dB;
    float al, be, ga;
    if (t == 0)              { dA =  1; dB =  2; al = -30.0f; be =  40.0f; ga = -10.0f; }
    else if (t == T_DIM - 1) { dA = -1; dB = -2; al =  30.0f; be = -40.0f; ga =  10.0f; }
    else                     { dA =  1; dB = -1; al =   0.0f; be =  10.0f; ga = -10.0f; }
    const float* __restrict__ pA = base + (ptrdiff_t)dA * TS_;
    const float* __restrict__ pB = base + (ptrdiff_t)dB * TS_;

    const float D   = ch ? 0.08f : 0.16f;
    const float Ff  = 0.06f, FpK = 0.122f;

    const size_t sp = (size_t)y0 * WW + col0;

    // ---- prologue: window = rows y0, y0+1 (middle-4) ; y0+2, y0+3 (full-8) ----
    float m40[4], m41[4], f80[8], f81[8];
    ldn(base + sp,           m40);
    ldn(base + sp + WW,      m41);
    ld8(base + sp + 2 * WW,  f80);
    ld8(base + sp + 3 * WW,  f81);

    float* __restrict__ outp = out + (size_t)ch * NOUT
                             + (size_t)(t * B_DIM + b) * OPLANE
                             + (size_t)y0 * OW + col0;

    #pragma unroll
    for (int i = 0; i < YT; i++) {
        const size_t ro = sp + (size_t)i * WW;     // input row y0+i

        // new bottom row (input row y+4), full 8 cols
        float f82[8];
        ld8(base + ro + 4 * WW, f82);

        // time-derivative planes + other-channel coupling: center row y+2, middle 4
        float A[4], Bv[4], O[4];
        ldn(pA + ro + 2 * WW, A);
        ldn(pB + ro + 2 * WW, Bv);
        ldn(po + ro + 2 * WW, O);

        float4 r;
        float* rr = &r.x;
        #pragma unroll
        for (int k = 0; k < 4; k++) {
            const float c = f80[k + 2];
            const float lap = (C1f * (f80[k + 1] + f80[k + 3] + m41[k] + f81[k + 2])
                             + C2f * (f80[k] + f80[k + 4] + m40[k] + f82[k + 2])
                             - 5.0f * c) * INV_DX2;
            const float uvv   = ch ? (O[k] * c * c) : (c * O[k] * O[k]);
            const float react = ch ? (uvv - FpK * c) : (Ff * (1.0f - c) - uvv);
            const float p = D * lap + react;
            rr[k] = p - (al * c + be * A[k] + ga * Bv[k]);
        }
        *reinterpret_cast<float4*>(outp + (size_t)i * OW) = r;

        // rotate window (pure renaming under full unroll)
        #pragma unroll
        for (int k = 0; k < 4; k++) { m40[k] = m41[k]; m41[k] = f80[k + 2]; }
        #pragma unroll
        for (int k = 0; k < 8; k++) { f80[k] = f81[k]; f81[k] = f82[k]; }
    }
}

extern "C" void kernel_launch(void* const* d_in, const int* in_sizes, int n_in,
                              void* d_out, int out_size)
{
    const float* in = (const float*)d_in[0];
    float* out = (float*)d_out;
    dim3 block(64, 2, 1);                 // ty=0 -> f_u warps, ty=1 -> f_v warps
    dim3 grid(OH / YT, T_DIM * B_DIM, 1); // 18 x 160 = 2880 CTAs
    grayscott_loss_kernel<<<grid, block>>>(in, out);
}